// round 12
// baseline (speedup 1.0000x reference)
#include <cuda_runtime.h>
#include <cuda_bf16.h>
#include <math.h>
#include <stdint.h>

// Problem constants
#define BB 256
#define SS 512
#define II 128
#define HH 256
#define J4H 1024          // 4*H gate width

// ---------------------------------------------------------------------------
// Scratch (device globals; no cudaMalloc allowed)
// ---------------------------------------------------------------------------
__device__ float g_G[(size_t)BB * SS * J4H];   // precomputed input gates
__device__ float g_Y1[(size_t)BB * SS * HH];   // layer-1 outputs

// ---------------------------------------------------------------------------
// bf16x3 tensor-core GEMM (unchanged from the 10.97ms pass):
//   C[n,j] = sum_k A[n,k]*W[j,k] + b1[j] + b2[j]     (J fixed = 1024)
// ---------------------------------------------------------------------------
#define AP 36

#define MMA_BF16(CREG, AREG, BREG)                                             \
    asm volatile(                                                              \
        "mma.sync.aligned.m16n8k16.row.col.f32.bf16.bf16.f32 "                 \
        "{%0,%1,%2,%3}, {%4,%5,%6,%7}, {%8,%9}, {%0,%1,%2,%3};"                \
        : "+f"(CREG[0]), "+f"(CREG[1]), "+f"(CREG[2]), "+f"(CREG[3])           \
        : "r"(AREG[0]), "r"(AREG[1]), "r"(AREG[2]), "r"(AREG[3]),              \
          "r"(BREG[0]), "r"(BREG[1]))

__global__ __launch_bounds__(256)
void gemm_bias_tc(const float* __restrict__ A,
                  const float* __restrict__ W,
                  const float* __restrict__ b1,
                  const float* __restrict__ b2,
                  float* __restrict__ C,
                  int K)
{
    __shared__ __nv_bfloat16 Ah[128][AP];
    __shared__ __nv_bfloat16 Al[128][AP];
    __shared__ __nv_bfloat16 Wh[64][AP];
    __shared__ __nv_bfloat16 Wl[64][AP];

    const int tid  = threadIdx.x;
    const int lane = tid & 31;
    const int warp = tid >> 5;
    const int wm   = warp & 3;
    const int wn   = warp >> 2;
    const int g    = lane >> 2;
    const int tg   = lane & 3;

    const int j0 = blockIdx.x * 64;
    const int n0 = blockIdx.y * 128;

    float acc[2][4][4];
#pragma unroll
    for (int mt = 0; mt < 2; mt++)
#pragma unroll
        for (int nt = 0; nt < 4; nt++)
#pragma unroll
            for (int i = 0; i < 4; i++) acc[mt][nt][i] = 0.f;

    float bs[4][2];
#pragma unroll
    for (int nt = 0; nt < 4; nt++) {
        int jc = j0 + wn * 32 + nt * 8 + 2 * tg;
        bs[nt][0] = b1[jc] + b2[jc];
        bs[nt][1] = b1[jc + 1] + b2[jc + 1];
    }

    for (int k0 = 0; k0 < K; k0 += 32) {
#pragma unroll
        for (int p = 0; p < 4; p++) {
            int id = tid + p * 256;
            int r  = id >> 3;
            int kc = (id & 7) * 4;
            float4 v = *(const float4*)&A[(size_t)(n0 + r) * K + k0 + kc];
            float vv[4] = {v.x, v.y, v.z, v.w};
#pragma unroll
            for (int i = 0; i < 4; i++) {
                __nv_bfloat16 hi = __float2bfloat16(vv[i]);
                Ah[r][kc + i] = hi;
                Al[r][kc + i] = __float2bfloat16(vv[i] - __bfloat162float(hi));
            }
        }
#pragma unroll
        for (int p = 0; p < 2; p++) {
            int id = tid + p * 256;
            int r  = id >> 3;
            int kc = (id & 7) * 4;
            float4 v = *(const float4*)&W[(size_t)(j0 + r) * K + k0 + kc];
            float vv[4] = {v.x, v.y, v.z, v.w};
#pragma unroll
            for (int i = 0; i < 4; i++) {
                __nv_bfloat16 hi = __float2bfloat16(vv[i]);
                Wh[r][kc + i] = hi;
                Wl[r][kc + i] = __float2bfloat16(vv[i] - __bfloat162float(hi));
            }
        }
        __syncthreads();

#pragma unroll
        for (int ks = 0; ks < 2; ks++) {
            const int c0 = ks * 16 + 2 * tg;

            uint32_t ah[2][4], al[2][4];
#pragma unroll
            for (int mt = 0; mt < 2; mt++) {
                int rb = wm * 32 + mt * 16;
                ah[mt][0] = *(const uint32_t*)&Ah[rb + g][c0];
                ah[mt][1] = *(const uint32_t*)&Ah[rb + g + 8][c0];
                ah[mt][2] = *(const uint32_t*)&Ah[rb + g][c0 + 8];
                ah[mt][3] = *(const uint32_t*)&Ah[rb + g + 8][c0 + 8];
                al[mt][0] = *(const uint32_t*)&Al[rb + g][c0];
                al[mt][1] = *(const uint32_t*)&Al[rb + g + 8][c0];
                al[mt][2] = *(const uint32_t*)&Al[rb + g][c0 + 8];
                al[mt][3] = *(const uint32_t*)&Al[rb + g + 8][c0 + 8];
            }
            uint32_t bh[4][2], bl[4][2];
#pragma unroll
            for (int nt = 0; nt < 4; nt++) {
                int jb = wn * 32 + nt * 8 + g;
                bh[nt][0] = *(const uint32_t*)&Wh[jb][c0];
                bh[nt][1] = *(const uint32_t*)&Wh[jb][c0 + 8];
                bl[nt][0] = *(const uint32_t*)&Wl[jb][c0];
                bl[nt][1] = *(const uint32_t*)&Wl[jb][c0 + 8];
            }

#pragma unroll
            for (int mt = 0; mt < 2; mt++)
#pragma unroll
                for (int nt = 0; nt < 4; nt++) {
                    float* c = acc[mt][nt];
                    MMA_BF16(c, ah[mt], bh[nt]);
                    MMA_BF16(c, al[mt], bh[nt]);
                    MMA_BF16(c, ah[mt], bl[nt]);
                }
        }
        __syncthreads();
    }

#pragma unroll
    for (int mt = 0; mt < 2; mt++) {
#pragma unroll
        for (int nt = 0; nt < 4; nt++) {
            int r0 = n0 + wm * 32 + mt * 16 + g;
            int jc = j0 + wn * 32 + nt * 8 + 2 * tg;
            float2 o0, o1;
            o0.x = acc[mt][nt][0] + bs[nt][0];
            o0.y = acc[mt][nt][1] + bs[nt][1];
            o1.x = acc[mt][nt][2] + bs[nt][0];
            o1.y = acc[mt][nt][3] + bs[nt][1];
            *(float2*)&C[(size_t)r0 * J4H + jc]       = o0;
            *(float2*)&C[(size_t)(r0 + 8) * J4H + jc] = o1;
        }
    }
}

// ---------------------------------------------------------------------------
// Tensor-core recurrent kernel with DSMEM h-exchange.
// Grid = 128 CTAs as 16 clusters of 8. Cluster c owns batch [16c,16c+16).
// CTA rank r owns h-cols [32r,32r+32) x 4 gates (local n in [0,128)).
// Warp w owns n-cols [16w,16w+16), FULL k=256 (no k-split / no reduction).
// h is exchanged via st.shared::cluster into every CTA's Hp buffer
// (packed u32: low16 = bf16 hi, high16 = bf16 lo), double-buffered.
// Sync: one hardware cluster barrier per step (also serves as CTA sync
// between gate-smem reads of step t-1 and writes of step t).
// ---------------------------------------------------------------------------
#define WPITCH 264        // bf16 elems per W smem row
#define HP32   264        // u32 elems per Hp row (16 rows per buffer)
#define GP32   136        // fp32 elems per gate smem row
// byte offsets in dynamic smem
#define SM_WH    0
#define SM_WL    (SM_WH + 128 * WPITCH * 2)          // 67584
#define SM_HP    (SM_WL + 128 * WPITCH * 2)          // 135168 (2*16*HP32*4)
#define SM_GT    (SM_HP + 2 * 16 * HP32 * 4)         // 168960 (16*GP32*4)
#define LSTM2_SMEM (SM_GT + 16 * GP32 * 4)           // 177664

__device__ __forceinline__ float sigf(float x) {
    return 1.0f / (1.0f + __expf(-x));
}
__device__ __forceinline__ float tanhfast(float x) {
    return 2.0f / (1.0f + __expf(-2.0f * x)) - 1.0f;
}
__device__ __forceinline__ uint32_t smem_u32(const void* p) {
    uint32_t a;
    asm("{ .reg .u64 t; cvta.to.shared.u64 t, %1; cvt.u32.u64 %0, t; }"
        : "=r"(a) : "l"(p));
    return a;
}

__global__ __launch_bounds__(256, 1) __cluster_dims__(8, 1, 1)
void lstm_tc_kernel(const float* __restrict__ G,
                    const float* __restrict__ Whh,
                    float* __restrict__ Y,
                    float* __restrict__ hOut,
                    float* __restrict__ cOut)
{
    extern __shared__ char smraw[];
    __nv_bfloat16* WhS = (__nv_bfloat16*)(smraw + SM_WH);
    __nv_bfloat16* WlS = (__nv_bfloat16*)(smraw + SM_WL);
    uint32_t* HpB      = (uint32_t*)(smraw + SM_HP);   // [2][16][HP32]
    float* SmGates     = (float*)(smraw + SM_GT);      // [16][GP32]

    const int tid   = threadIdx.x;
    const int lane  = tid & 31;
    const int warp  = tid >> 5;        // n-band: cols [16w,16w+16)
    const int g     = lane >> 2;       // 0..7
    const int tg    = lane & 3;        // 0..3
    const int rank  = blockIdx.x & 7;  // h band
    const int cid   = blockIdx.x >> 3; // batch tile
    const int b0    = cid * 16;
    const int hbase = rank * 32;

    // ---- Load + split Whh slice: 128 rows (g4*256 + hbase + jl) x 256 ----
    for (int i = tid; i < 128 * 64; i += 256) {
        int row = i >> 6;              // local n = g4*32 + jl
        int kc  = (i & 63) * 4;
        int g4  = row >> 5;
        int jl  = row & 31;
        float4 v = *(const float4*)
            &Whh[(size_t)(g4 * 256 + hbase + jl) * 256 + kc];
        float vv[4] = {v.x, v.y, v.z, v.w};
#pragma unroll
        for (int ii = 0; ii < 4; ii++) {
            __nv_bfloat16 hi = __float2bfloat16(vv[ii]);
            WhS[row * WPITCH + kc + ii] = hi;
            WlS[row * WPITCH + kc + ii] =
                __float2bfloat16(vv[ii] - __bfloat162float(hi));
        }
    }
    __syncthreads();

    // ---- Per-thread ownership for epilogue: 2 (b, jl) pairs ----
    // pp=0: b = tid>>5 (0..7), pp=1: b+8. Same jl for both.
    const int jl  = tid & 31;
    const int bE  = tid >> 5;          // 0..7
    size_t gofs[2], yofs[2], hofs[2];
#pragma unroll
    for (int pp = 0; pp < 2; pp++) {
        int b = bE + 8 * pp;
        gofs[pp] = ((size_t)(b0 + b) * SS) * J4H + hbase + jl;
        yofs[pp] = ((size_t)(b0 + b) * SS) * HH + hbase + jl;
        hofs[pp] = (size_t)(b0 + b) * HH + hbase + jl;
    }
    float cS[2] = {0.f, 0.f};

    // Local smem addresses of this thread's Hp slots (write side)
    const uint32_t hpAddr0 =
        smem_u32(&HpB[0 * 16 * HP32 + bE * HP32 + hbase + jl]);
    const uint32_t hpStride = 8 * HP32 * 4;     // pp stride (8 batch rows)
    const uint32_t hpBufBytes = 16 * HP32 * 4;  // buffer stride

    // Prefetch t=0 gate inputs
    float pre[2][4];
#pragma unroll
    for (int pp = 0; pp < 2; pp++)
#pragma unroll
        for (int g4 = 0; g4 < 4; g4++)
            pre[pp][g4] = __ldcg(&G[gofs[pp] + g4 * 256]);

    for (int t = 0; t < SS; t++) {
        if (t > 0) {
            // ---- MMA: acc[16 x 16band] over full k=256, from packed Hp ----
            const uint32_t* hp = HpB + (size_t)(t & 1) * 16 * HP32;
            float acc[2][4];
#pragma unroll
            for (int nt = 0; nt < 2; nt++)
#pragma unroll
                for (int i = 0; i < 4; i++) acc[nt][i] = 0.f;

#pragma unroll
            for (int kt = 0; kt < 16; kt++) {
                const int c0 = kt * 16 + 2 * tg;
                uint2 w00 = *(const uint2*)&hp[g * HP32 + c0];
                uint2 w01 = *(const uint2*)&hp[(g + 8) * HP32 + c0];
                uint2 w10 = *(const uint2*)&hp[g * HP32 + c0 + 8];
                uint2 w11 = *(const uint2*)&hp[(g + 8) * HP32 + c0 + 8];
                uint32_t ah[4], al[4];
                ah[0] = __byte_perm(w00.x, w00.y, 0x5410);
                al[0] = __byte_perm(w00.x, w00.y, 0x7632);
                ah[1] = __byte_perm(w01.x, w01.y, 0x5410);
                al[1] = __byte_perm(w01.x, w01.y, 0x7632);
                ah[2] = __byte_perm(w10.x, w10.y, 0x5410);
                al[2] = __byte_perm(w10.x, w10.y, 0x7632);
                ah[3] = __byte_perm(w11.x, w11.y, 0x5410);
                al[3] = __byte_perm(w11.x, w11.y, 0x7632);
#pragma unroll
                for (int nt = 0; nt < 2; nt++) {
                    int jb = 16 * warp + 8 * nt + g;
                    uint32_t bh[2], bl[2];
                    bh[0] = *(const uint32_t*)&WhS[jb * WPITCH + c0];
                    bh[1] = *(const uint32_t*)&WhS[jb * WPITCH + c0 + 8];
                    bl[0] = *(const uint32_t*)&WlS[jb * WPITCH + c0];
                    bl[1] = *(const uint32_t*)&WlS[jb * WPITCH + c0 + 8];
                    float* c = acc[nt];
                    MMA_BF16(c, ah, bh);
                    MMA_BF16(c, al, bh);
                    MMA_BF16(c, ah, bl);
                }
            }

            // ---- Stage gates to smem (single sync, no k-reduction) ----
#pragma unroll
            for (int nt = 0; nt < 2; nt++) {
                int col = 16 * warp + 8 * nt + 2 * tg;
                float2 v0 = make_float2(acc[nt][0], acc[nt][1]);
                float2 v1 = make_float2(acc[nt][2], acc[nt][3]);
                *(float2*)&SmGates[g * GP32 + col]       = v0;
                *(float2*)&SmGates[(g + 8) * GP32 + col] = v1;
            }
            __syncthreads();
        }

        // ---- Epilogue: gates -> nonlinearity -> state -> h exchange ----
        float hv[2];
        uint32_t packed[2];
#pragma unroll
        for (int pp = 0; pp < 2; pp++) {
            int b = bE + 8 * pp;
            float gi = pre[pp][0], gf = pre[pp][1];
            float gg = pre[pp][2], go = pre[pp][3];
            if (t > 0) {
                const float* row = &SmGates[b * GP32 + jl];
                gi += row[0];
                gf += row[32];
                gg += row[64];
                go += row[96];
            }
            float iv = sigf(gi), fv = sigf(gf);
            float gv = tanhfast(gg), ov = sigf(go);
            cS[pp] = fv * cS[pp] + iv * gv;
            hv[pp] = ov * tanhfast(cS[pp]);

            __nv_bfloat16 hi = __float2bfloat16(hv[pp]);
            __nv_bfloat16 lo =
                __float2bfloat16(hv[pp] - __bfloat162float(hi));
            packed[pp] = (uint32_t)__bfloat16_as_ushort(hi) |
                         ((uint32_t)__bfloat16_as_ushort(lo) << 16);
        }

        // Broadcast h to ALL cluster CTAs' Hp write-buffer via DSMEM.
        {
            const uint32_t la0 =
                hpAddr0 + (uint32_t)(((t + 1) & 1)) * hpBufBytes;
#pragma unroll
            for (int rk = 0; rk < 8; rk++) {
                uint32_t r0;
                asm volatile("mapa.shared::cluster.u32 %0, %1, %2;"
                             : "=r"(r0) : "r"(la0), "r"(rk));
                asm volatile("st.shared::cluster.u32 [%0], %1;"
                             :: "r"(r0), "r"(packed[0]) : "memory");
                asm volatile("st.shared::cluster.u32 [%0], %1;"
                             :: "r"(r0 + hpStride), "r"(packed[1]) : "memory");
            }
        }

        if (hOut != nullptr && t == SS - 1) {
#pragma unroll
            for (int pp = 0; pp < 2; pp++) {
                hOut[hofs[pp]] = hv[pp];
                cOut[hofs[pp]] = cS[pp];
            }
        }

        // Release DSMEM h-writes to the cluster.
        asm volatile("barrier.cluster.arrive.aligned;" ::: "memory");

        // Global Y store + next-step G prefetch overlap the barrier wait.
#pragma unroll
        for (int pp = 0; pp < 2; pp++)
            Y[yofs[pp] + (size_t)t * HH] = hv[pp];
        if (t + 1 < SS) {
#pragma unroll
            for (int pp = 0; pp < 2; pp++)
#pragma unroll
                for (int g4 = 0; g4 < 4; g4++)
                    pre[pp][g4] =
                        __ldcg(&G[gofs[pp] + (size_t)(t + 1) * J4H + g4 * 256]);
        }

        asm volatile("barrier.cluster.wait.aligned;" ::: "memory");
    }
}

// ---------------------------------------------------------------------------
// Launch
// ---------------------------------------------------------------------------
extern "C" void kernel_launch(void* const* d_in, const int* in_sizes, int n_in,
                              void* d_out, int out_size)
{
    (void)in_sizes; (void)n_in; (void)out_size;
    const float* x    = (const float*)d_in[0];
    const float* Wih0 = (const float*)d_in[1];
    const float* Whh0 = (const float*)d_in[2];
    const float* bih0 = (const float*)d_in[3];
    const float* bhh0 = (const float*)d_in[4];
    const float* Wih1 = (const float*)d_in[5];
    const float* Whh1 = (const float*)d_in[6];
    const float* bih1 = (const float*)d_in[7];
    const float* bhh1 = (const float*)d_in[8];

    float* y    = (float*)d_out;                        // [B,S,H]
    float* hOut = y + (size_t)BB * SS * HH;             // [1,B,H]
    float* cOut = hOut + (size_t)BB * HH;               // [1,B,H]

    void *pG = nullptr, *pY1 = nullptr;
    cudaGetSymbolAddress(&pG, g_G);
    cudaGetSymbolAddress(&pY1, g_Y1);

    cudaFuncSetAttribute(lstm_tc_kernel,
                         cudaFuncAttributeMaxDynamicSharedMemorySize,
                         LSTM2_SMEM);

    dim3 gemm_grid(J4H / 64, (BB * SS) / 128);

    // Layer 1
    gemm_bias_tc<<<gemm_grid, 256>>>(x, Wih0, bih0, bhh0, (float*)pG, II);
    lstm_tc_kernel<<<128, 256, LSTM2_SMEM>>>(
        (const float*)pG, Whh0, (float*)pY1, nullptr, nullptr);

    // Layer 2
    gemm_bias_tc<<<gemm_grid, 256>>>((const float*)pY1, Wih1, bih1, bhh1,
                                     (float*)pG, HH);
    lstm_tc_kernel<<<128, 256, LSTM2_SMEM>>>(
        (const float*)pG, Whh1, y, hOut, cOut);
}